// round 13
// baseline (speedup 1.0000x reference)
#include <cuda_runtime.h>
#include <cuda_bf16.h>
#include <math.h>

// ---------------------------------------------------------------------------
// AVWDCRNN: adaptive-graph-conv GRU with HiPPO c-state.
// B=64, T=12, N=307, Din=Dout=64, L=2, De=16, K=5 supports.
// Round 13 (base = passing R12): gate/cand per-node GEMMs now build their A
// (activation) mma fragments DIRECTLY from global memory in registers
// (analytic m16n8k16 fragment layout), removing the A smem+ldmatrix path.
// Smem holds only weight tiles -> k-tile 32 double-buffered fits statically;
// barriers per block halved (gate 60->30, cand 40->20). bf16 3-term math and
// k-order unchanged. tgemm/support/epilogue code identical to R12.
// ---------------------------------------------------------------------------

#define NNODE 307
#define BB    64
#define TT    12
#define DOUT  64
#define DE    16
#define KSUP  5
#define KR    4
#define CG    192
#define CC    128
#define GK    (KSUP*CG)      // 960
#define CK    (KSUP*CC)      // 640
#define NN    (NNODE*NNODE)
#define NB    (NNODE*BB)
#define NBO   (NB*DOUT)
#define TNBO  (TT*NBO)
#define MG    (KR*NNODE)     // 1228
#define KTPAD 320

// ------------------------------- scratch -----------------------------------
__device__ float g_SS [KR*NN];
__device__ __nv_bfloat16 g_Shi[MG*KTPAD];
__device__ __nv_bfloat16 g_Slo[MG*KTPAD];
__device__ __nv_bfloat16 g_Wgh[NNODE*GK*128];
__device__ __nv_bfloat16 g_Wgl[NNODE*GK*128];
__device__ float g_bgn[NNODE*128];
__device__ __nv_bfloat16 g_Wch[NNODE*CK*64];
__device__ __nv_bfloat16 g_Wcl[NNODE*CK*64];
__device__ float g_bcn[NNODE*64];
__device__ float g_XA [TNBO];
__device__ float g_HS [TNBO];
__device__ float g_XIN[NB*CG];
__device__ float g_RH [NB*DOUT];
__device__ float g_XG [KR*NB*CG];
__device__ float g_XGR[KR*NB*DOUT];
__device__ float g_Z  [NB*DOUT];

// --------------------------- asm helpers ------------------------------------
__device__ __forceinline__ void ldsm_x4(unsigned* r, unsigned addr) {
    asm volatile("ldmatrix.sync.aligned.m8n8.x4.shared.b16 {%0,%1,%2,%3}, [%4];"
                 : "=r"(r[0]), "=r"(r[1]), "=r"(r[2]), "=r"(r[3]) : "r"(addr));
}
__device__ __forceinline__ void ldsm_x4t(unsigned* r, unsigned addr) {
    asm volatile("ldmatrix.sync.aligned.m8n8.x4.trans.shared.b16 {%0,%1,%2,%3}, [%4];"
                 : "=r"(r[0]), "=r"(r[1]), "=r"(r[2]), "=r"(r[3]) : "r"(addr));
}
__device__ __forceinline__ void mma16816(float* d, const unsigned* a, const unsigned* b) {
    asm volatile("mma.sync.aligned.m16n8k16.row.col.f32.bf16.bf16.f32 "
                 "{%0,%1,%2,%3},{%4,%5,%6,%7},{%8,%9},{%0,%1,%2,%3};"
                 : "+f"(d[0]), "+f"(d[1]), "+f"(d[2]), "+f"(d[3])
                 : "r"(a[0]), "r"(a[1]), "r"(a[2]), "r"(a[3]), "r"(b[0]), "r"(b[1]));
}
__device__ __forceinline__ void split2(float x, float y, __nv_bfloat162* hi, __nv_bfloat162* lo) {
    __nv_bfloat16 h0 = __float2bfloat16(x), h1 = __float2bfloat16(y);
    *hi = __halves2bfloat162(h0, h1);
    *lo = __halves2bfloat162(__float2bfloat16(x - __bfloat162float(h0)),
                             __float2bfloat16(y - __bfloat162float(h1)));
}

// ------------------------- supports construction ----------------------------
__global__ void build_A_kernel(const float* __restrict__ E, float* __restrict__ A) {
    __shared__ float row[NNODE];
    __shared__ float er[DE];
    __shared__ float red[256];
    int i = blockIdx.x, tid = threadIdx.x;
    if (tid < DE) er[tid] = E[i*DE + tid];
    __syncthreads();
    for (int j = tid; j < NNODE; j += 256) {
        float s = 0.f;
        #pragma unroll
        for (int d = 0; d < DE; d++) s += er[d] * E[j*DE + d];
        row[j] = fmaxf(s, 0.f);
    }
    __syncthreads();
    float m = -1e30f;
    for (int j = tid; j < NNODE; j += 256) m = fmaxf(m, row[j]);
    red[tid] = m; __syncthreads();
    for (int s = 128; s > 0; s >>= 1) { if (tid < s) red[tid] = fmaxf(red[tid], red[tid+s]); __syncthreads(); }
    m = red[0]; __syncthreads();
    float sum = 0.f;
    for (int j = tid; j < NNODE; j += 256) { float e = expf(row[j]-m); row[j] = e; sum += e; }
    red[tid] = sum; __syncthreads();
    for (int s = 128; s > 0; s >>= 1) { if (tid < s) red[tid] += red[tid+s]; __syncthreads(); }
    float inv = 1.f / red[0];
    for (int j = tid; j < NNODE; j += 256) A[i*NNODE + j] = row[j] * inv;
}

__global__ void build_adjn_kernel(const float* __restrict__ adj, float* __restrict__ out) {
    __shared__ float red[256];
    int i = blockIdx.x, tid = threadIdx.x;
    float sum = 0.f;
    for (int j = tid; j < NNODE; j += 256) sum += adj[i*NNODE + j];
    red[tid] = sum; __syncthreads();
    for (int s = 128; s > 0; s >>= 1) { if (tid < s) red[tid] += red[tid+s]; __syncthreads(); }
    float inv = 1.f / (red[0] + 1e-8f);
    for (int j = tid; j < NNODE; j += 256) out[i*NNODE + j] = adj[i*NNODE + j] * inv;
}

__global__ void cheb_fix_kernel(float* __restrict__ S1) {
    int idx = blockIdx.x*blockDim.x + threadIdx.x;
    if (idx >= NN) return;
    float v = 2.f * S1[idx];
    if (idx / NNODE == idx % NNODE) v -= 1.f;
    S1[idx] = v;
}

__global__ void split_S_kernel(const float* __restrict__ SS,
                               __nv_bfloat16* __restrict__ Shi,
                               __nv_bfloat16* __restrict__ Slo) {
    int idx = blockIdx.x*blockDim.x + threadIdx.x;
    if (idx >= MG*KTPAD) return;
    int m = idx / KTPAD, k = idx % KTPAD;
    float v = (k < NNODE) ? SS[m*NNODE + k] : 0.f;
    __nv_bfloat16 h = __float2bfloat16(v);
    Shi[idx] = h;
    Slo[idx] = __float2bfloat16(v - __bfloat162float(h));
}

// ------------------------- generic SGEMM (row-major) ------------------------
__global__ __launch_bounds__(256)
void sgemm_kernel(int M, int N, int K,
                  const float* __restrict__ A, int lda,
                  const float* __restrict__ B, int ldb,
                  float* __restrict__ C, int ldc)
{
    __shared__ float As[8][128];
    __shared__ float Bs[8][128];
    int tid = threadIdx.x;
    int m0 = blockIdx.y * 128;
    int n0 = blockIdx.x * 128;
    int tx = tid % 16, ty = tid / 16;
    float acc[8][8];
    #pragma unroll
    for (int i = 0; i < 8; i++)
        #pragma unroll
        for (int j = 0; j < 8; j++) acc[i][j] = 0.f;

    int arow = tid / 2;
    int acol = (tid % 2) * 4;
    int brow = tid / 32;
    int bcol = (tid % 32) * 4;

    for (int kt = 0; kt < K; kt += 8) {
        #pragma unroll
        for (int j = 0; j < 4; j++) {
            int m = m0 + arow, k = kt + acol + j;
            As[acol + j][arow] = (m < M && k < K) ? A[(long long)m*lda + k] : 0.f;
        }
        #pragma unroll
        for (int j = 0; j < 4; j++) {
            int k = kt + brow, n = n0 + bcol + j;
            Bs[brow][bcol + j] = (k < K && n < N) ? B[(long long)k*ldb + n] : 0.f;
        }
        __syncthreads();
        #pragma unroll
        for (int kk = 0; kk < 8; kk++) {
            float a[8], b[8];
            #pragma unroll
            for (int i = 0; i < 4; i++) { a[i] = As[kk][ty*4+i]; a[4+i] = As[kk][64+ty*4+i]; }
            #pragma unroll
            for (int j = 0; j < 4; j++) { b[j] = Bs[kk][tx*4+j]; b[4+j] = Bs[kk][64+tx*4+j]; }
            #pragma unroll
            for (int i = 0; i < 8; i++)
                #pragma unroll
                for (int j = 0; j < 8; j++) acc[i][j] += a[i] * b[j];
        }
        __syncthreads();
    }
    #pragma unroll
    for (int i = 0; i < 8; i++) {
        int m = m0 + (i < 4 ? ty*4+i : 64 + ty*4 + (i-4));
        if (m >= M) continue;
        #pragma unroll
        for (int j = 0; j < 8; j++) {
            int n = n0 + (j < 4 ? tx*4+j : 64 + tx*4 + (j-4));
            if (n < N) C[(long long)m*ldc + n] = acc[i][j];
        }
    }
}

// --------------- tensor-core support GEMM: C = S @ B (unchanged R12) --------
__global__ __launch_bounds__(256)
void tgemm_kernel(int M, int N,
                  const __nv_bfloat16* __restrict__ Ah,
                  const __nv_bfloat16* __restrict__ Al,
                  const float* __restrict__ B, int ldb,
                  float* __restrict__ C, int ldc)
{
    __shared__ __nv_bfloat16 sAh[2][128][24];
    __shared__ __nv_bfloat16 sAl[2][128][24];
    __shared__ __nv_bfloat16 sBh[2][16][136];
    __shared__ __nv_bfloat16 sBl[2][16][136];

    int tid  = threadIdx.x;
    int warp = tid >> 5, lane = tid & 31;
    int m0 = blockIdx.y * 128, n0 = blockIdx.x * 128;
    int wm = (warp >> 2) * 64, wn = (warp & 3) * 32;

    float acc[4][4][4];
    #pragma unroll
    for (int i = 0; i < 4; i++)
        #pragma unroll
        for (int j = 0; j < 4; j++)
            #pragma unroll
            for (int q = 0; q < 4; q++) acc[i][j][q] = 0.f;

    int ar = tid >> 1, ac = (tid & 1) * 8;
    int bk = tid >> 4, bn = (tid & 15) * 8;

    int srow = m0 + ar; if (srow > M-1) srow = M-1;
    const __nv_bfloat16* gAh = Ah + (long long)srow*KTPAD + ac;
    const __nv_bfloat16* gAl = Al + (long long)srow*KTPAD + ac;

    uint4 rah, ral;
    float4 rb0, rb1;

#define TG_LOAD(kt_) {                                                            \
    rah = *(const uint4*)(gAh + (kt_)*16);                                        \
    ral = *(const uint4*)(gAl + (kt_)*16);                                        \
    int kg = (kt_)*16 + bk;                                                       \
    if (kg < NNODE) { const float* gb = B + (long long)kg*ldb + n0 + bn;          \
        rb0 = *(const float4*)gb; rb1 = *(const float4*)(gb + 4); }               \
    else { rb0 = rb1 = make_float4(0.f,0.f,0.f,0.f); } }

#define TG_STORE(buf_) {                                                          \
    *(uint4*)&sAh[buf_][ar][ac] = rah;                                            \
    *(uint4*)&sAl[buf_][ar][ac] = ral;                                            \
    __nv_bfloat16* dh = &sBh[buf_][bk][bn]; __nv_bfloat16* dl = &sBl[buf_][bk][bn]; \
    split2(rb0.x, rb0.y, (__nv_bfloat162*)dh,     (__nv_bfloat162*)dl);           \
    split2(rb0.z, rb0.w, (__nv_bfloat162*)(dh+2), (__nv_bfloat162*)(dl+2));       \
    split2(rb1.x, rb1.y, (__nv_bfloat162*)(dh+4), (__nv_bfloat162*)(dl+4));       \
    split2(rb1.z, rb1.w, (__nv_bfloat162*)(dh+6), (__nv_bfloat162*)(dl+6)); }

    const int NT = KTPAD/16;   // 20
    TG_LOAD(0);
    int cur = 0;
    for (int kt = 0; kt < NT; kt++) {
        TG_STORE(cur);
        __syncthreads();
        if (kt + 1 < NT) TG_LOAD(kt+1);

        unsigned afh[4][4], afl[4][4], bfh[4][2], bfl[4][2];
        #pragma unroll
        for (int mi = 0; mi < 4; mi++) {
            int row = wm + mi*16 + (lane & 15);
            int col = (lane >> 4) * 8;
            ldsm_x4(afh[mi], (unsigned)__cvta_generic_to_shared(&sAh[cur][row][col]));
            ldsm_x4(afl[mi], (unsigned)__cvta_generic_to_shared(&sAl[cur][row][col]));
        }
        #pragma unroll
        for (int np = 0; np < 2; np++) {
            int k  = lane & 15;
            int nn = wn + np*16 + (lane >> 4) * 8;
            unsigned r[4];
            ldsm_x4t(r, (unsigned)__cvta_generic_to_shared(&sBh[cur][k][nn]));
            bfh[np*2][0] = r[0]; bfh[np*2][1] = r[1];
            bfh[np*2+1][0] = r[2]; bfh[np*2+1][1] = r[3];
            ldsm_x4t(r, (unsigned)__cvta_generic_to_shared(&sBl[cur][k][nn]));
            bfl[np*2][0] = r[0]; bfl[np*2][1] = r[1];
            bfl[np*2+1][0] = r[2]; bfl[np*2+1][1] = r[3];
        }
        #pragma unroll
        for (int mi = 0; mi < 4; mi++)
            #pragma unroll
            for (int ni = 0; ni < 4; ni++) {
                mma16816(acc[mi][ni], afh[mi], bfh[ni]);
                mma16816(acc[mi][ni], afh[mi], bfl[ni]);
                mma16816(acc[mi][ni], afl[mi], bfh[ni]);
            }
        cur ^= 1;
    }

    int g = lane >> 2, tq = lane & 3;
    #pragma unroll
    for (int mi = 0; mi < 4; mi++) {
        #pragma unroll
        for (int ni = 0; ni < 4; ni++) {
            int row = m0 + wm + mi*16 + g;
            int col = n0 + wn + ni*8 + tq*2;
            if (row < M)
                *(float2*)&C[(long long)row*ldc + col] = make_float2(acc[mi][ni][0], acc[mi][ni][1]);
            if (row + 8 < M)
                *(float2*)&C[(long long)(row+8)*ldc + col] = make_float2(acc[mi][ni][2], acc[mi][ni][3]);
        }
    }
#undef TG_LOAD
#undef TG_STORE
}

// ---------------------- per-node weight projection (bf16 hi/lo) -------------
__global__ void project_Wg_kernel(const float* __restrict__ E, const float* __restrict__ Wg,
                                  __nv_bfloat16* __restrict__ Wh, __nv_bfloat16* __restrict__ Wl, int l) {
    int kc = blockIdx.x, n = blockIdx.y, o = threadIdx.x;
    const float* er = E + n*DE;
    float acc = 0.f;
    #pragma unroll
    for (int d = 0; d < DE; d++) acc += er[d] * Wg[((l*DE + d)*GK + kc)*128 + o];
    __nv_bfloat16 h = __float2bfloat16(acc);
    long long idx = ((long long)n*GK + kc)*128 + o;
    Wh[idx] = h;
    Wl[idx] = __float2bfloat16(acc - __bfloat162float(h));
}
__global__ void project_Wc_kernel(const float* __restrict__ E, const float* __restrict__ Wc,
                                  __nv_bfloat16* __restrict__ Wh, __nv_bfloat16* __restrict__ Wl, int l) {
    int kc = blockIdx.x, n = blockIdx.y, o = threadIdx.x;
    const float* er = E + n*DE;
    float acc = 0.f;
    #pragma unroll
    for (int d = 0; d < DE; d++) acc += er[d] * Wc[((l*DE + d)*CK + kc)*64 + o];
    __nv_bfloat16 h = __float2bfloat16(acc);
    long long idx = ((long long)n*CK + kc)*64 + o;
    Wh[idx] = h;
    Wl[idx] = __float2bfloat16(acc - __bfloat162float(h));
}
__global__ void project_bg_kernel(const float* __restrict__ E, const float* __restrict__ bg,
                                  float* __restrict__ bgn, int l) {
    int n = blockIdx.x, o = threadIdx.x;
    float acc = 0.f;
    #pragma unroll
    for (int d = 0; d < DE; d++) acc += E[n*DE+d] * bg[(l*DE + d)*128 + o];
    bgn[n*128 + o] = acc;
}
__global__ void project_bc_kernel(const float* __restrict__ E, const float* __restrict__ bc,
                                  float* __restrict__ bcn, int l) {
    int n = blockIdx.x, o = threadIdx.x;
    float acc = 0.f;
    #pragma unroll
    for (int d = 0; d < DE; d++) acc += E[n*DE+d] * bc[(l*DE + d)*64 + o];
    bcn[n*64 + o] = acc;
}

// ----------------------------- data movement --------------------------------
__global__ void window_avg_l0_kernel(const float* __restrict__ x, float* __restrict__ XA) {
    long long idx = (long long)blockIdx.x*blockDim.x + threadIdx.x;
    if (idx >= TNBO) return;
    int c = (int)(idx % DOUT);
    int b = (int)((idx / DOUT) % BB);
    int n = (int)((idx / (DOUT*BB)) % NNODE);
    int t = (int)(idx / ((long long)DOUT*BB*NNODE));
    long long base = (((long long)b*TT + t)*NNODE + n)*DOUT + c;
    const long long dT = (long long)NNODE*DOUT;
    float v;
    if (t == 0 || t == TT-1) v = x[base];
    else v = (x[base - dT] + x[base] + x[base + dT]) * (1.f/3.f);
    XA[idx] = v;
}

__global__ void window_avg_kernel(const float* __restrict__ IN, float* __restrict__ XA) {
    int idx = blockIdx.x*blockDim.x + threadIdx.x;
    if (idx >= TNBO) return;
    int t = idx / NBO;
    if (t == 0 || t == TT-1) XA[idx] = IN[idx];
    else XA[idx] = (IN[idx-NBO] + IN[idx] + IN[idx+NBO]) * (1.f/3.f);
}

// seeds h,c AND x(t=0) into XIN
__global__ void init_state_kernel(const float* __restrict__ h0, const float* __restrict__ c0,
                                  const float* __restrict__ XA, float* __restrict__ XIN, int l) {
    int idx = blockIdx.x*blockDim.x + threadIdx.x;
    if (idx >= NBO) return;
    int o = idx % DOUT;
    int b = (idx / DOUT) % BB;
    int n = idx / (DOUT*BB);
    int src = ((l*BB + b)*NNODE + n)*DOUT + o;
    XIN[(n*BB + b)*CG + o]       = XA[idx];
    XIN[(n*BB + b)*CG + 64  + o] = h0[src];
    XIN[(n*BB + b)*CG + 128 + o] = c0[src];
}

// -------- gate: per-node TC GEMM (64x128x960) + sigmoid + r*h ---------------
// A fragments built directly from global (no A smem); B double-buffered,
// k-tile 32, ONE sync per tile. bf16 3-term.
__global__ __launch_bounds__(256)
void gate_tc_kernel(const float* __restrict__ XG, const float* __restrict__ XIN,
                    const __nv_bfloat16* __restrict__ Wh, const __nv_bfloat16* __restrict__ Wl,
                    const float* __restrict__ bgn,
                    float* __restrict__ Z, float* __restrict__ RH)
{
    const int n = blockIdx.x;
    __shared__ __nv_bfloat16 sBh[2][32][136], sBl[2][32][136];
    int tid = threadIdx.x, warp = tid >> 5, lane = tid & 31;
    int wm = (warp >> 1) * 16, wn = (warp & 1) * 64;
    int g = lane >> 2, t2 = (lane & 3) * 2;

    float acc[8][4];
    #pragma unroll
    for (int i = 0; i < 8; i++)
        #pragma unroll
        for (int q = 0; q < 4; q++) acc[i][q] = 0.f;

    int br = tid >> 3, bc16 = (tid & 7) * 16;   // B: 32 rows x 128 halves
    const __nv_bfloat16* Wnh = Wh + (long long)n * GK * 128;
    const __nv_bfloat16* Wnl = Wl + (long long)n * GK * 128;

    uint4 rbh0, rbh1, rbl0, rbl1;

#define GT_LOAD(kt_) { int kk0 = (kt_)*32;                                        \
    const __nv_bfloat16* gh = Wnh + (long long)(kk0 + br)*128 + bc16;              \
    const __nv_bfloat16* gl = Wnl + (long long)(kk0 + br)*128 + bc16;              \
    rbh0 = *(const uint4*)gh; rbh1 = *(const uint4*)(gh + 8);                      \
    rbl0 = *(const uint4*)gl; rbl1 = *(const uint4*)(gl + 8); }

#define GT_STORE(buf_) {                                                          \
    *(uint4*)&sBh[buf_][br][bc16]     = rbh0; *(uint4*)&sBh[buf_][br][bc16 + 8] = rbh1; \
    *(uint4*)&sBl[buf_][br][bc16]     = rbl0; *(uint4*)&sBl[buf_][br][bc16 + 8] = rbl1; }

    const int NT = GK/32;   // 30
    GT_LOAD(0);
    int cur = 0;
    for (int kt = 0; kt < NT; kt++) {
        GT_STORE(cur);
        __syncthreads();
        if (kt + 1 < NT) GT_LOAD(kt+1);

        int kk0 = kt * 32;
        int ksup = kk0 / CG, cb = kk0 % CG;
        const float* Abase = (ksup == 0)
            ? XIN + (long long)(n*BB)*CG
            : XG  + (((long long)(ksup-1)*NNODE + n)*BB)*CG;

        #pragma unroll
        for (int ks = 0; ks < 2; ks++) {
            // ---- A fragment direct from global (rows wm+g, wm+g+8) ----
            const float* ab = Abase + cb + ks*16;
            const float* r0p = ab + (long long)(wm + g)*CG;
            const float* r1p = ab + (long long)(wm + g + 8)*CG;
            float2 p00 = *(const float2*)(r0p + t2);
            float2 p10 = *(const float2*)(r1p + t2);
            float2 p01 = *(const float2*)(r0p + t2 + 8);
            float2 p11 = *(const float2*)(r1p + t2 + 8);
            unsigned ah[4], al[4];
            split2(p00.x, p00.y, (__nv_bfloat162*)&ah[0], (__nv_bfloat162*)&al[0]);
            split2(p10.x, p10.y, (__nv_bfloat162*)&ah[1], (__nv_bfloat162*)&al[1]);
            split2(p01.x, p01.y, (__nv_bfloat162*)&ah[2], (__nv_bfloat162*)&al[2]);
            split2(p11.x, p11.y, (__nv_bfloat162*)&ah[3], (__nv_bfloat162*)&al[3]);

            unsigned bh[8][2], bl[8][2];
            #pragma unroll
            for (int np = 0; np < 4; np++) {
                int k  = ks*16 + (lane & 15);
                int nn = wn + np*16 + (lane >> 4) * 8;
                unsigned r[4];
                ldsm_x4t(r, (unsigned)__cvta_generic_to_shared(&sBh[cur][k][nn]));
                bh[np*2][0] = r[0]; bh[np*2][1] = r[1];
                bh[np*2+1][0] = r[2]; bh[np*2+1][1] = r[3];
                ldsm_x4t(r, (unsigned)__cvta_generic_to_shared(&sBl[cur][k][nn]));
                bl[np*2][0] = r[0]; bl[np*2][1] = r[1];
                bl[np*2+1][0] = r[2]; bl[np*2+1][1] = r[3];
            }
            #pragma unroll
            for (int ni = 0; ni < 8; ni++) {
                mma16816(acc[ni], ah, bh[ni]);
                mma16816(acc[ni], ah, bl[ni]);
                mma16816(acc[ni], al, bh[ni]);
            }
        }
        cur ^= 1;
    }

    const float* brow = bgn + n*128;
    int q = lane & 3;
    #pragma unroll
    for (int ni = 0; ni < 8; ni++) {
        #pragma unroll
        for (int d = 0; d < 4; d++) {
            int row = wm + g + ((d >= 2) ? 8 : 0);
            int col = wn + ni*8 + q*2 + (d & 1);
            float v = acc[ni][d] + brow[col];
            float s = 1.f / (1.f + expf(-v));
            if (col < 64) {
                Z[(n*BB + row)*DOUT + col] = s;
            } else {
                int oo = col - 64;
                float h = XIN[(long long)(n*BB + row)*CG + 64 + oo];
                RH[(n*BB + row)*DOUT + oo] = s * h;
            }
        }
    }
#undef GT_LOAD
#undef GT_STORE
}

// ------- candidate: per-node TC GEMM (64x64x640) + tanh + GRU/HiPPO ---------
// Direct-register A fragments, B double-buffered, k-tile 32, one sync/tile.
__global__ __launch_bounds__(256)
void cand_tc_kernel(const float* __restrict__ XG, const float* __restrict__ XIN,
                    const float* __restrict__ RH, const float* __restrict__ XGR,
                    const __nv_bfloat16* __restrict__ Wh, const __nv_bfloat16* __restrict__ Wl,
                    const float* __restrict__ bcn, const float* __restrict__ Z,
                    const float* __restrict__ XA,
                    float* __restrict__ XINout, float* __restrict__ OUT,
                    int t, int is_final, float ca, float cb)
{
    const int n = blockIdx.x;
    __shared__ __nv_bfloat16 sBh[2][32][72], sBl[2][32][72];
    int tid = threadIdx.x, warp = tid >> 5, lane = tid & 31;
    int wm = (warp >> 1) * 16, wn = (warp & 1) * 32;
    int g = lane >> 2, t2 = (lane & 3) * 2;

    float acc[4][4];
    #pragma unroll
    for (int i = 0; i < 4; i++)
        #pragma unroll
        for (int q = 0; q < 4; q++) acc[i][q] = 0.f;

    int br = tid >> 3, bc8 = (tid & 7) * 8;     // B: 32 rows x 64 halves
    const __nv_bfloat16* Wnh = Wh + (long long)n * CK * 64;
    const __nv_bfloat16* Wnl = Wl + (long long)n * CK * 64;

    uint4 rbh, rbl;

#define CD_LOAD(kt_) { int kk0 = (kt_)*32;                                        \
    rbh = *(const uint4*)(Wnh + (long long)(kk0 + br)*64 + bc8);                   \
    rbl = *(const uint4*)(Wnl + (long long)(kk0 + br)*64 + bc8); }

#define CD_STORE(buf_) {                                                          \
    *(uint4*)&sBh[buf_][br][bc8] = rbh;                                            \
    *(uint4*)&sBl[buf_][br][bc8] = rbl; }

    const int NT = CK/32;   // 20
    CD_LOAD(0);
    int cur = 0;
    for (int kt = 0; kt < NT; kt++) {
        CD_STORE(cur);
        __syncthreads();
        if (kt + 1 < NT) CD_LOAD(kt+1);

        int kk0 = kt * 32;
        int ksup = kk0 / CC, cw = kk0 % CC;
        const float* Abase; long long astride;
        if (cw < 64) {
            astride = CG;
            Abase = (ksup == 0) ? XIN + (long long)(n*BB)*CG + cw
                                : XG  + (((long long)(ksup-1)*NNODE + n)*BB)*CG + cw;
        } else {
            astride = DOUT;
            Abase = (ksup == 0) ? RH  + (long long)(n*BB)*DOUT + (cw - 64)
                                : XGR + (((long long)(ksup-1)*NNODE + n)*BB)*DOUT + (cw - 64);
        }

        #pragma unroll
        for (int ks = 0; ks < 2; ks++) {
            const float* ab = Abase + ks*16;
            const float* r0p = ab + (long long)(wm + g)*astride;
            const float* r1p = ab + (long long)(wm + g + 8)*astride;
            float2 p00 = *(const float2*)(r0p + t2);
            float2 p10 = *(const float2*)(r1p + t2);
            float2 p01 = *(const float2*)(r0p + t2 + 8);
            float2 p11 = *(const float2*)(r1p + t2 + 8);
            unsigned ah[4], al[4];
            split2(p00.x, p00.y, (__nv_bfloat162*)&ah[0], (__nv_bfloat162*)&al[0]);
            split2(p10.x, p10.y, (__nv_bfloat162*)&ah[1], (__nv_bfloat162*)&al[1]);
            split2(p01.x, p01.y, (__nv_bfloat162*)&ah[2], (__nv_bfloat162*)&al[2]);
            split2(p11.x, p11.y, (__nv_bfloat162*)&ah[3], (__nv_bfloat162*)&al[3]);

            unsigned bh[4][2], bl[4][2];
            #pragma unroll
            for (int np = 0; np < 2; np++) {
                int k  = ks*16 + (lane & 15);
                int nn = wn + np*16 + (lane >> 4) * 8;
                unsigned r[4];
                ldsm_x4t(r, (unsigned)__cvta_generic_to_shared(&sBh[cur][k][nn]));
                bh[np*2][0] = r[0]; bh[np*2][1] = r[1];
                bh[np*2+1][0] = r[2]; bh[np*2+1][1] = r[3];
                ldsm_x4t(r, (unsigned)__cvta_generic_to_shared(&sBl[cur][k][nn]));
                bl[np*2][0] = r[0]; bl[np*2][1] = r[1];
                bl[np*2+1][0] = r[2]; bl[np*2+1][1] = r[3];
            }
            #pragma unroll
            for (int ni = 0; ni < 4; ni++) {
                mma16816(acc[ni], ah, bh[ni]);
                mma16816(acc[ni], ah, bl[ni]);
                mma16816(acc[ni], al, bh[ni]);
            }
        }
        cur ^= 1;
    }

    const float* brow = bcn + n*64;
    int q = lane & 3;
    #pragma unroll
    for (int ni = 0; ni < 4; ni++) {
        #pragma unroll
        for (int d = 0; d < 4; d++) {
            int row = wm + g + ((d >= 2) ? 8 : 0);
            int col = wn + ni*8 + q*2 + (d & 1);
            float hc = tanhf(acc[ni][d] + brow[col]);
            float z  = Z[(n*BB + row)*DOUT + col];
            long long ih = (long long)(n*BB + row)*CG + 64 + col;
            float h_old = XINout[ih];
            float c_old = XINout[ih + 64];
            float h_new = z*h_old + (1.f - z)*hc;
            float c_new = ca*c_old + cb*h_new;
            XINout[ih]      = h_new;
            XINout[ih + 64] = c_new;
            if (is_final) OUT[(((long long)row*TT + t)*NNODE + n)*DOUT + col] = h_new;
            else          OUT[(((long long)t*NNODE + n)*BB + row)*DOUT + col] = h_new;
            if (t + 1 < TT)   // stage next step's x (replaces prep_step)
                XINout[(long long)(n*BB + row)*CG + col] =
                    XA[(long long)(t+1)*NBO + (n*BB + row)*DOUT + col];
        }
    }
#undef CD_LOAD
#undef CD_STORE
}

// -------------------------------- driver ------------------------------------
extern "C" void kernel_launch(void* const* d_in, const int* in_sizes, int n_in,
                              void* d_out, int out_size)
{
    const float* x   = (const float*)d_in[0];
    const float* h0  = (const float*)d_in[1];
    const float* c0  = (const float*)d_in[2];
    const float* E   = (const float*)d_in[3];
    const float* adj = (const float*)d_in[4];
    const float* Wg  = (const float*)d_in[5];
    const float* bg  = (const float*)d_in[6];
    const float* Wc  = (const float*)d_in[7];
    const float* bc  = (const float*)d_in[8];
    float* out = (float*)d_out;
    (void)in_sizes; (void)n_in; (void)out_size;

    float *SS, *bgn, *bcn, *XA, *HS, *XIN, *RH, *XG, *XGR, *Z;
    __nv_bfloat16 *Shi, *Slo, *Wgh, *Wgl, *Wch, *Wcl;
    cudaGetSymbolAddress((void**)&SS,  g_SS);
    cudaGetSymbolAddress((void**)&Shi, g_Shi);
    cudaGetSymbolAddress((void**)&Slo, g_Slo);
    cudaGetSymbolAddress((void**)&Wgh, g_Wgh);
    cudaGetSymbolAddress((void**)&Wgl, g_Wgl);
    cudaGetSymbolAddress((void**)&bgn, g_bgn);
    cudaGetSymbolAddress((void**)&Wch, g_Wch);
    cudaGetSymbolAddress((void**)&Wcl, g_Wcl);
    cudaGetSymbolAddress((void**)&bcn, g_bcn);
    cudaGetSymbolAddress((void**)&XA,  g_XA);
    cudaGetSymbolAddress((void**)&HS,  g_HS);
    cudaGetSymbolAddress((void**)&XIN, g_XIN);
    cudaGetSymbolAddress((void**)&RH,  g_RH);
    cudaGetSymbolAddress((void**)&XG,  g_XG);
    cudaGetSymbolAddress((void**)&XGR, g_XGR);
    cudaGetSymbolAddress((void**)&Z,   g_Z);

    // ---- supports ----
    build_A_kernel   <<<NNODE, 256>>>(E,   SS + 0*NN);
    build_adjn_kernel<<<NNODE, 256>>>(adj, SS + 2*NN);
    dim3 g307((NNODE+127)/128, (NNODE+127)/128);
    sgemm_kernel<<<g307, 256>>>(NNODE, NNODE, NNODE, SS+0*NN, NNODE, SS+0*NN, NNODE, SS+1*NN, NNODE);
    cheb_fix_kernel<<<(NN+255)/256, 256>>>(SS + 1*NN);
    sgemm_kernel<<<g307, 256>>>(NNODE, NNODE, NNODE, SS+2*NN, NNODE, SS+2*NN, NNODE, SS+3*NN, NNODE);
    split_S_kernel<<<(MG*KTPAD + 255)/256, 256>>>(SS, Shi, Slo);

    for (int l = 0; l < 2; l++) {
        if (l == 0) window_avg_l0_kernel<<<(TNBO+255)/256, 256>>>(x, XA);
        else        window_avg_kernel   <<<(TNBO+255)/256, 256>>>(HS, XA);
        project_Wg_kernel<<<dim3(GK, NNODE), 128>>>(E, Wg, Wgh, Wgl, l);
        project_bg_kernel<<<NNODE, 128>>>(E, bg, bgn, l);
        project_Wc_kernel<<<dim3(CK, NNODE), 64>>>(E, Wc, Wch, Wcl, l);
        project_bc_kernel<<<NNODE, 64>>>(E, bc, bcn, l);
        init_state_kernel<<<(NBO+255)/256, 256>>>(h0, c0, XA, XIN, l);

        for (int t = 0; t < TT; t++) {
            // XG = S @ XIN  (1228 x 12288 x 307)
            dim3 g1((BB*CG)/128, (MG+127)/128);
            tgemm_kernel<<<g1, 256>>>(MG, BB*CG, Shi, Slo, XIN, BB*CG, XG, BB*CG);

            gate_tc_kernel<<<NNODE, 256>>>(XG, XIN, Wgh, Wgl, bgn, Z, RH);

            // XGR = S @ RH  (1228 x 4096 x 307)
            dim3 g3((BB*DOUT)/128, (MG+127)/128);
            tgemm_kernel<<<g3, 256>>>(MG, BB*DOUT, Shi, Slo, RH, BB*DOUT, XGR, BB*DOUT);

            float ca = (float)t / (float)(t + 1);
            float cb = 1.f / (float)(t + 1);
            cand_tc_kernel<<<NNODE, 256>>>(XG, XIN, RH, XGR, Wch, Wcl, bcn, Z, XA, XIN,
                                           (l == 1) ? out : HS, t, (l == 1), ca, cb);
        }
    }
}